// round 1
// baseline (speedup 1.0000x reference)
#include <cuda_runtime.h>

// Problem dims
#define BB 16
#define WORDS 32
#define DIM 256
#define HEADS 8
#define DH 32
#define INNER 256
#define JJ 256     // WORDS*HEADS
#define IW 32      // output capsules (WORDS)
#define EE 256     // INNER

#define U_BSTRIDE ((size_t)JJ * IW * EE)   // 2,097,152 floats per batch in u_hat

// ---------------- scratch (device globals; no allocations) ----------------
__device__ float g_xh[BB * JJ * DH];                 // [b][j][d]
__device__ float g_u[(size_t)BB * JJ * IW * EE];     // [b][j][i][e]  (128 MiB)
__device__ float g_S[3][BB * IW * EE];               // s accumulators per iter
__device__ float g_V[3][BB * IW * EE];               // v per iter
__device__ float g_blog[BB * JJ * IW];               // routing logits (const over e)

// ---------------- f32x2 helpers (Blackwell FFMA2 path) ----------------
typedef unsigned long long u64;

__device__ __forceinline__ u64 pack2(float lo, float hi) {
    u64 r;
    asm("mov.b64 %0, {%1, %2};" : "=l"(r)
        : "r"(__float_as_uint(lo)), "r"(__float_as_uint(hi)));
    return r;
}
__device__ __forceinline__ void unpack2(u64 v, float& lo, float& hi) {
    unsigned a, b;
    asm("mov.b64 {%0, %1}, %2;" : "=r"(a), "=r"(b) : "l"(v));
    lo = __uint_as_float(a);
    hi = __uint_as_float(b);
}
__device__ __forceinline__ void fma2(u64& acc, u64 a, u64 b) {
    asm("fma.rn.f32x2 %0, %1, %2, %0;" : "+l"(acc) : "l"(a), "l"(b));
}
__device__ __forceinline__ void add2(u64& acc, u64 a) {
    asm("add.rn.f32x2 %0, %1, %2;" : "=l"(acc) : "l"(acc), "l"(a));
}

// ---------------- K0: zero the s accumulators ----------------
__global__ void k_zero() {
    int t = blockIdx.x * 256 + threadIdx.x;
    ((float*)g_S)[t] = 0.0f;   // grid sized exactly to 3*BB*IW*EE
}

// ---------------- K1: inner projection  xh[b][j][d] ----------------
// xi[b,n,ee] = sum_k x[b,n,k] * Wi[ee,k] + bi[ee];  j = n*8 + ee/32, d = ee%32
__global__ void __launch_bounds__(256) k_proj_in(const float* __restrict__ x,
                                                 const float* __restrict__ Wi,
                                                 const float* __restrict__ bi) {
    int b  = blockIdx.y;   // 0..15
    int eb = blockIdx.x;   // 0..7  (block of 32 ee)
    __shared__ float xs[32][DIM];   // [n][k]
    __shared__ float ws[32][33];    // Wi tile [ee_local][k_local], padded

    int tid = threadIdx.x;
    const float4* xg = (const float4*)(x + (size_t)b * 32 * DIM);
    float4* xs4 = (float4*)xs;
    for (int idx = tid; idx < 32 * DIM / 4; idx += 256) xs4[idx] = xg[idx];

    int el = tid & 31;
    int n0 = (tid >> 5) * 4;
    float acc[4] = {0.f, 0.f, 0.f, 0.f};

    for (int kt = 0; kt < 8; kt++) {
        __syncthreads();
        {
            int r = tid >> 5, c = tid & 31;
            for (int rr = r; rr < 32; rr += 8)
                ws[rr][c] = Wi[(size_t)(eb * 32 + rr) * DIM + kt * 32 + c];
        }
        __syncthreads();
#pragma unroll
        for (int k = 0; k < 32; k++) {
            float wv = ws[el][k];
#pragma unroll
            for (int r = 0; r < 4; r++)
                acc[r] = fmaf(xs[n0 + r][kt * 32 + k], wv, acc[r]);
        }
    }

    int ee = eb * 32 + el;
    float bv = bi[ee];
    int h = ee >> 5, d = ee & 31;
#pragma unroll
    for (int r = 0; r < 4; r++) {
        int n = n0 + r;
        g_xh[((size_t)b * JJ + n * HEADS + h) * DH + d] = acc[r] + bv;
    }
}

// ---------------- K2: u_hat einsum + fused iter-0 sum over j ----------------
// u[b,j,i,e] = sum_d W[j,i,e,d] * xh[b,j,d] + bias[j,i,e]
// Also accumulates S0[b,i,e] += sum_j u  (uniform-c iteration folded in).
__global__ void __launch_bounds__(256) k_uhat(const float* __restrict__ W,
                                              const float* __restrict__ bias) {
    int i  = blockIdx.y;   // 0..31
    int jb = blockIdx.x;   // 0..31 -> j = jb*8 + jj
    int e  = threadIdx.x;  // 0..255

    __shared__ __align__(16) float sxh[8][32][16];  // [jj][d][b]  (16 KB)
    for (int idx = threadIdx.x; idx < 8 * 512; idx += 256) {
        int jj = idx >> 9;
        int rem = idx & 511;
        int b = rem >> 5;
        int d = rem & 31;
        sxh[jj][d][b] = g_xh[((size_t)b * JJ + jb * 8 + jj) * DH + d];
    }
    __syncthreads();

    u64 sacc[8];
#pragma unroll
    for (int p = 0; p < 8; p++) sacc[p] = 0ull;

    for (int jj = 0; jj < 8; jj++) {
        int j = jb * 8 + jj;
        const float4* wp =
            (const float4*)(W + (((size_t)j * IW + i) * EE + e) * DH);
        float4 w4[8];
#pragma unroll
        for (int q = 0; q < 8; q++) w4[q] = wp[q];
        float bv = bias[((size_t)j * IW + i) * EE + e];

        u64 acc[8];
#pragma unroll
        for (int p = 0; p < 8; p++) acc[p] = 0ull;

#pragma unroll
        for (int q = 0; q < 8; q++) {
            float4 wq = w4[q];
#pragma unroll
            for (int c = 0; c < 4; c++) {
                float wv = (c == 0) ? wq.x : (c == 1) ? wq.y : (c == 2) ? wq.z : wq.w;
                int d = q * 4 + c;
                u64 w2 = pack2(wv, wv);
                const ulonglong2* row = (const ulonglong2*)&sxh[jj][d][0];
#pragma unroll
                for (int m = 0; m < 4; m++) {
                    ulonglong2 xv = row[m];
                    fma2(acc[2 * m], w2, xv.x);
                    fma2(acc[2 * m + 1], w2, xv.y);
                }
            }
        }

        u64 b2 = pack2(bv, bv);
        size_t base = (size_t)j * (IW * EE) + (size_t)i * EE + e;
#pragma unroll
        for (int p = 0; p < 8; p++) {
            u64 uv = acc[p];
            add2(uv, b2);         // add bias
            add2(sacc[p], uv);    // iter-0 accumulation (sum over j)
            float lo, hi;
            unpack2(uv, lo, hi);
            g_u[base + (size_t)(2 * p) * U_BSTRIDE]     = lo;
            g_u[base + (size_t)(2 * p + 1) * U_BSTRIDE] = hi;
        }
    }

#pragma unroll
    for (int p = 0; p < 8; p++) {
        float lo, hi;
        unpack2(sacc[p], lo, hi);
        atomicAdd(&g_S[0][(2 * p) * (IW * EE) + i * EE + e], lo);
        atomicAdd(&g_S[0][(2 * p + 1) * (IW * EE) + i * EE + e], hi);
    }
}

// ---------------- squash: v = s * n/(1+n^2), n = ||s|| ----------------
__global__ void __launch_bounds__(256) k_squash(int si, int vi, float scale) {
    int bi = blockIdx.x;       // (b*32 + i)
    int t  = threadIdx.x;
    float s = g_S[si][bi * EE + t] * scale;
    float ss = s * s;
#pragma unroll
    for (int o = 16; o; o >>= 1) ss += __shfl_xor_sync(0xffffffffu, ss, o);
    __shared__ float red[8];
    if ((t & 31) == 0) red[t >> 5] = ss;
    __syncthreads();
    float n2 = 0.f;
#pragma unroll
    for (int q = 0; q < 8; q++) n2 += red[q];
    float f = sqrtf(n2) / (1.0f + n2);
    g_V[vi][bi * EE + t] = s * f;
}

// ---------------- routing pass: agreements + softmax + weighted sum ----------------
// PASS==1: a = dot(u, v_in); store blog = a;            c = softmax_i(a)
// PASS==2: a = dot(u, v_in); c = softmax_i(blog + a)
template <int PASS>
__global__ void __launch_bounds__(256) k_route(int vin_idx, int sout_idx) {
    int jb = blockIdx.x;   // 0..31
    int b  = blockIdx.y;   // 0..15
    int tid = threadIdx.x, w = tid >> 5, l = tid & 31;

    __shared__ float vs[IW][EE];   // 32 KB
    __shared__ float a_s[IW];
    __shared__ float c_s[IW];

    const float4* vg4 = (const float4*)(g_V[vin_idx] + (size_t)b * IW * EE);
    float4* vs4 = (float4*)vs;
    for (int idx = tid; idx < IW * EE / 4; idx += 256) vs4[idx] = vg4[idx];
    __syncthreads();

    float sacc[4][8];
#pragma unroll
    for (int s = 0; s < 4; s++)
#pragma unroll
        for (int k = 0; k < 8; k++) sacc[s][k] = 0.f;

    for (int jj = 0; jj < 8; jj++) {
        int j = jb * 8 + jj;
        const float* ub = g_u + (size_t)b * U_BSTRIDE + (size_t)j * (IW * EE);

        float ur[4][8];
#pragma unroll
        for (int s = 0; s < 4; s++) {
            int i = w + s * 8;
            const float4* up = (const float4*)(ub + i * EE);
            float4 a = up[l];
            float4 c = up[l + 32];
            ur[s][0] = a.x; ur[s][1] = a.y; ur[s][2] = a.z; ur[s][3] = a.w;
            ur[s][4] = c.x; ur[s][5] = c.y; ur[s][6] = c.z; ur[s][7] = c.w;
        }
#pragma unroll
        for (int s = 0; s < 4; s++) {
            int i = w + s * 8;
            const float4* vp = (const float4*)(&vs[i][0]);
            float4 va = vp[l];
            float4 vc = vp[l + 32];
            float dot = ur[s][0] * va.x + ur[s][1] * va.y + ur[s][2] * va.z +
                        ur[s][3] * va.w + ur[s][4] * vc.x + ur[s][5] * vc.y +
                        ur[s][6] * vc.z + ur[s][7] * vc.w;
#pragma unroll
            for (int o = 16; o; o >>= 1) dot += __shfl_xor_sync(0xffffffffu, dot, o);
            if (l == 0) a_s[i] = dot;
        }
        __syncthreads();
        if (w == 0) {
            float z = a_s[l];
            if (PASS == 2) {
                z += g_blog[((size_t)b * JJ + j) * IW + l];
            } else {
                g_blog[((size_t)b * JJ + j) * IW + l] = z;
            }
            float mx = z;
#pragma unroll
            for (int o = 16; o; o >>= 1) mx = fmaxf(mx, __shfl_xor_sync(0xffffffffu, mx, o));
            float p = __expf(z - mx);
            float sm = p;
#pragma unroll
            for (int o = 16; o; o >>= 1) sm += __shfl_xor_sync(0xffffffffu, sm, o);
            c_s[l] = p / sm;
        }
        __syncthreads();
#pragma unroll
        for (int s = 0; s < 4; s++) {
            float c = c_s[w + s * 8];
#pragma unroll
            for (int k = 0; k < 8; k++) sacc[s][k] = fmaf(c, ur[s][k], sacc[s][k]);
        }
    }

    float* So = g_S[sout_idx] + (size_t)b * IW * EE;
#pragma unroll
    for (int s = 0; s < 4; s++) {
        int i = w + s * 8;
#pragma unroll
        for (int k = 0; k < 8; k++) {
            int e = (k < 4) ? (l * 4 + k) : (128 + l * 4 + (k - 4));
            atomicAdd(&So[i * EE + e], sacc[s][k]);
        }
    }
}

// ---------------- K8: output projection  out = v2 @ Wo^T + bo ----------------
__global__ void __launch_bounds__(256) k_proj_out(const float* __restrict__ Wo,
                                                  const float* __restrict__ bo,
                                                  float* __restrict__ out) {
    int b  = blockIdx.y;   // 0..15
    int db = blockIdx.x;   // 0..7
    __shared__ float vvs[32][EE];
    __shared__ float wos[32][33];

    int tid = threadIdx.x;
    const float4* vg4 = (const float4*)(g_V[2] + (size_t)b * IW * EE);
    float4* vv4 = (float4*)vvs;
    for (int idx = tid; idx < IW * EE / 4; idx += 256) vv4[idx] = vg4[idx];

    int dl = tid & 31;
    int n0 = (tid >> 5) * 4;
    float acc[4] = {0.f, 0.f, 0.f, 0.f};

    for (int et = 0; et < 8; et++) {
        __syncthreads();
        {
            int r = tid >> 5, c = tid & 31;
            for (int rr = r; rr < 32; rr += 8)
                wos[rr][c] = Wo[(size_t)(db * 32 + rr) * EE + et * 32 + c];
        }
        __syncthreads();
#pragma unroll
        for (int k = 0; k < 32; k++) {
            float wv = wos[dl][k];
#pragma unroll
            for (int r = 0; r < 4; r++)
                acc[r] = fmaf(vvs[n0 + r][et * 32 + k], wv, acc[r]);
        }
    }

    int dm = db * 32 + dl;
    float bv = bo[dm];
#pragma unroll
    for (int r = 0; r < 4; r++)
        out[((size_t)b * WORDS + n0 + r) * DIM + dm] = acc[r] + bv;
}

// ---------------- launch ----------------
extern "C" void kernel_launch(void* const* d_in, const int* in_sizes, int n_in,
                              void* d_out, int out_size) {
    const float* x    = (const float*)d_in[0];
    const float* W    = (const float*)d_in[1];
    const float* bias = (const float*)d_in[2];
    const float* Wi   = (const float*)d_in[3];
    const float* bi   = (const float*)d_in[4];
    const float* Wo   = (const float*)d_in[5];
    const float* bo   = (const float*)d_in[6];
    float* out = (float*)d_out;

    k_zero<<<(3 * BB * IW * EE) / 256, 256>>>();
    k_proj_in<<<dim3(8, BB), 256>>>(x, Wi, bi);
    k_uhat<<<dim3(32, 32), 256>>>(W, bias);
    k_squash<<<BB * IW, 256>>>(0, 0, 1.0f / 32.0f);   // v0 from mean over j
    k_route<1><<<dim3(32, BB), 256>>>(0, 1);           // a0 -> blog, S1
    k_squash<<<BB * IW, 256>>>(1, 1, 1.0f);            // v1
    k_route<2><<<dim3(32, BB), 256>>>(1, 2);           // softmax(blog+a1), S2
    k_squash<<<BB * IW, 256>>>(2, 2, 1.0f);            // v2
    k_proj_out<<<dim3(8, BB), 256>>>(Wo, bo, out);
}

// round 3
// speedup vs baseline: 1.0956x; 1.0956x over previous
#include <cuda_runtime.h>

// Problem dims
#define BB 16
#define WORDS 32
#define DIM 256
#define HEADS 8
#define DH 32
#define INNER 256
#define JJ 256     // WORDS*HEADS
#define IW 32      // output capsules (WORDS)
#define EE 256     // INNER

#define U_BSTRIDE ((size_t)JJ * IW * EE)   // elements per batch in u_hat

// ---------------- scratch (device globals; no allocations) ----------------
__device__ float g_xh[BB * JJ * DH];                  // [b][j][d]
__device__ float g_u[(size_t)BB * JJ * IW * EE];      // [b][j][i][e]  (128 MiB)
__device__ float g_S[3][BB * IW * EE];                // s accumulators per iter
__device__ float g_V[3][BB * IW * EE];                // v per iter
__device__ float g_blog[BB * JJ * IW];                // routing logits

// ---------------- f32x2 helpers ----------------
typedef unsigned long long u64;

__device__ __forceinline__ u64 pack2(float lo, float hi) {
    u64 r;
    asm("mov.b64 %0, {%1, %2};" : "=l"(r)
        : "r"(__float_as_uint(lo)), "r"(__float_as_uint(hi)));
    return r;
}
__device__ __forceinline__ void unpack2(u64 v, float& lo, float& hi) {
    unsigned a, b;
    asm("mov.b64 {%0, %1}, %2;" : "=r"(a), "=r"(b) : "l"(v));
    lo = __uint_as_float(a);
    hi = __uint_as_float(b);
}
__device__ __forceinline__ void fma2(u64& acc, u64 a, u64 b) {
    asm("fma.rn.f32x2 %0, %1, %2, %0;" : "+l"(acc) : "l"(a), "l"(b));
}
__device__ __forceinline__ void add2(u64& acc, u64 a) {
    asm("add.rn.f32x2 %0, %1, %2;" : "=l"(acc) : "l"(acc), "l"(a));
}

// ---------------- K0: zero the s accumulators (vectorized) ----------------
__global__ void k_zero() {
    int t = blockIdx.x * 256 + threadIdx.x;
    ((float4*)g_S)[t] = make_float4(0.f, 0.f, 0.f, 0.f);
}

// ---------------- K1: inner projection  xh[b][j][d] ----------------
__global__ void __launch_bounds__(256) k_proj_in(const float* __restrict__ x,
                                                 const float* __restrict__ Wi,
                                                 const float* __restrict__ bi) {
    int b  = blockIdx.y;
    int eb = blockIdx.x;
    __shared__ float xs[32][DIM];
    __shared__ float ws[32][33];

    int tid = threadIdx.x;
    const float4* xg = (const float4*)(x + (size_t)b * 32 * DIM);
    float4* xs4 = (float4*)xs;
    for (int idx = tid; idx < 32 * DIM / 4; idx += 256) xs4[idx] = xg[idx];

    int el = tid & 31;
    int n0 = (tid >> 5) * 4;
    float acc[4] = {0.f, 0.f, 0.f, 0.f};

    for (int kt = 0; kt < 8; kt++) {
        __syncthreads();
        {
            int r = tid >> 5, c = tid & 31;
            for (int rr = r; rr < 32; rr += 8)
                ws[rr][c] = Wi[(size_t)(eb * 32 + rr) * DIM + kt * 32 + c];
        }
        __syncthreads();
#pragma unroll
        for (int k = 0; k < 32; k++) {
            float wv = ws[el][k];
#pragma unroll
            for (int r = 0; r < 4; r++)
                acc[r] = fmaf(xs[n0 + r][kt * 32 + k], wv, acc[r]);
        }
    }

    int ee = eb * 32 + el;
    float bv = bi[ee];
    int h = ee >> 5, d = ee & 31;
#pragma unroll
    for (int r = 0; r < 4; r++) {
        int n = n0 + r;
        g_xh[((size_t)b * JJ + n * HEADS + h) * DH + d] = acc[r] + bv;
    }
}

// ---------------- K2: u_hat einsum (+ fused iter-0 sum over j) ----------------
// u[b,j,i,e] = sum_d W[j,i,e,d]*xh[b,j,d] + bias[j,i,e]   (fp32 storage)
// W staged through XOR-swizzled shared tile for coalesced global reads.
__global__ void __launch_bounds__(256, 2) k_uhat(const float* __restrict__ W,
                                                 const float* __restrict__ bias) {
    int i  = blockIdx.y;   // 0..31
    int jb = blockIdx.x;   // 0..31 -> j = jb*8 + jj
    int e  = threadIdx.x;  // 0..255

    __shared__ __align__(16) float sxh[8][32][16];  // [jj][d][b]  16 KB
    __shared__ __align__(16) float4 s_w[2048];      // swizzled W tile 32 KB

    for (int idx = threadIdx.x; idx < 8 * 512; idx += 256) {
        int jj  = idx >> 9;
        int rem = idx & 511;
        int b   = rem >> 5;
        int d   = rem & 31;
        sxh[jj][d][b] = g_xh[((size_t)b * JJ + jb * 8 + jj) * DH + d];
    }

    u64 sacc[8];
#pragma unroll
    for (int p = 0; p < 8; p++) sacc[p] = 0ull;

    for (int jj = 0; jj < 8; jj++) {
        int j = jb * 8 + jj;
        const float4* Wg = (const float4*)W + ((size_t)j * IW + i) * 2048;

        __syncthreads();   // s_w free to refill (covers sxh fill on jj==0)
#pragma unroll
        for (int k = 0; k < 8; k++) {
            int idx = threadIdx.x + k * 256;   // coalesced: warp = 512B contiguous
            int er = idx >> 3, q = idx & 7;
            s_w[(er << 3) | (q ^ (er & 7))] = Wg[idx];
        }
        float bv = bias[((size_t)j * IW + i) * EE + e];
        __syncthreads();

        float4 w4[8];
#pragma unroll
        for (int q = 0; q < 8; q++) w4[q] = s_w[(e << 3) | (q ^ (e & 7))];

        u64 acc[8];
#pragma unroll
        for (int p = 0; p < 8; p++) acc[p] = 0ull;

#pragma unroll
        for (int q = 0; q < 8; q++) {
            float4 wq = w4[q];
#pragma unroll
            for (int c = 0; c < 4; c++) {
                float wv = (c == 0) ? wq.x : (c == 1) ? wq.y : (c == 2) ? wq.z : wq.w;
                int d = q * 4 + c;
                u64 w2 = pack2(wv, wv);
                const ulonglong2* row = (const ulonglong2*)&sxh[jj][d][0];
#pragma unroll
                for (int m = 0; m < 4; m++) {
                    ulonglong2 xv = row[m];
                    fma2(acc[2 * m], w2, xv.x);
                    fma2(acc[2 * m + 1], w2, xv.y);
                }
            }
        }

        u64 b2 = pack2(bv, bv);
        size_t base = (size_t)j * (IW * EE) + (size_t)i * EE + e;
#pragma unroll
        for (int p = 0; p < 8; p++) {
            u64 uv = acc[p];
            add2(uv, b2);         // + bias
            add2(sacc[p], uv);    // fused iter-0 accumulation
            float lo, hi;
            unpack2(uv, lo, hi);
            g_u[base + (size_t)(2 * p) * U_BSTRIDE]     = lo;
            g_u[base + (size_t)(2 * p + 1) * U_BSTRIDE] = hi;
        }
    }

#pragma unroll
    for (int p = 0; p < 8; p++) {
        float lo, hi;
        unpack2(sacc[p], lo, hi);
        atomicAdd(&g_S[0][(2 * p) * (IW * EE) + i * EE + e], lo);
        atomicAdd(&g_S[0][(2 * p + 1) * (IW * EE) + i * EE + e], hi);
    }
}

// ---------------- squash: v = s * n/(1+n^2) ----------------
__global__ void __launch_bounds__(256) k_squash(int si, int vi, float scale) {
    int bi = blockIdx.x;       // (b*32 + i)
    int t  = threadIdx.x;
    float s = g_S[si][bi * EE + t] * scale;
    float ss = s * s;
#pragma unroll
    for (int o = 16; o; o >>= 1) ss += __shfl_xor_sync(0xffffffffu, ss, o);
    __shared__ float red[8];
    if ((t & 31) == 0) red[t >> 5] = ss;
    __syncthreads();
    float n2 = 0.f;
#pragma unroll
    for (int q = 0; q < 8; q++) n2 += red[q];
    float f = sqrtf(n2) / (1.0f + n2);
    g_V[vi][bi * EE + t] = s * f;
}

// ---------------- routing pass over fp32 u ----------------
// PASS==1: a = dot(u, v_in); blog = a;       c = softmax_i(a)
// PASS==2: a = dot(u, v_in); c = softmax_i(blog + a)
template <int PASS>
__global__ void __launch_bounds__(256, 2) k_route(int vin_idx, int sout_idx) {
    int jb = blockIdx.x;   // 0..15 -> 16 j per block
    int b  = blockIdx.y;   // 0..15
    int tid = threadIdx.x, w = tid >> 5, l = tid & 31;

    __shared__ float vs[IW][EE];   // 32 KB
    __shared__ float a_s[IW];
    __shared__ float c_s[IW];

    const float4* vg4 = (const float4*)(g_V[vin_idx] + (size_t)b * IW * EE);
    float4* vs4 = (float4*)vs;
    for (int idx = tid; idx < IW * EE / 4; idx += 256) vs4[idx] = vg4[idx];
    __syncthreads();

    float4 sacc[4][2];
#pragma unroll
    for (int s = 0; s < 4; s++) {
        sacc[s][0] = make_float4(0.f, 0.f, 0.f, 0.f);
        sacc[s][1] = make_float4(0.f, 0.f, 0.f, 0.f);
    }

    const float* ubase = g_u + (size_t)b * U_BSTRIDE;

    // prefetch first j (each lane: 8 consecutive floats = 2x float4)
    float4 cur[4][2];
    {
        int j0 = jb * 16;
#pragma unroll
        for (int s = 0; s < 4; s++) {
            int i = w + s * 8;
            const float4* up = (const float4*)(ubase + ((size_t)j0 * IW + i) * EE + l * 8);
            cur[s][0] = up[0];
            cur[s][1] = up[1];
        }
    }

    for (int jj = 0; jj < 16; jj++) {
        int j = jb * 16 + jj;

        // prefetch next j
        float4 nxt[4][2];
        if (jj < 15) {
            int jn = j + 1;
#pragma unroll
            for (int s = 0; s < 4; s++) {
                int i = w + s * 8;
                const float4* up = (const float4*)(ubase + ((size_t)jn * IW + i) * EE + l * 8);
                nxt[s][0] = up[0];
                nxt[s][1] = up[1];
            }
        }

        // agreement dots
#pragma unroll
        for (int s = 0; s < 4; s++) {
            int i = w + s * 8;
            const float4* vp = (const float4*)(&vs[i][l * 8]);
            float4 va = vp[0];
            float4 vc = vp[1];
            float4 a = cur[s][0], c4 = cur[s][1];
            float dot = a.x * va.x + a.y * va.y + a.z * va.z + a.w * va.w +
                        c4.x * vc.x + c4.y * vc.y + c4.z * vc.z + c4.w * vc.w;
#pragma unroll
            for (int o = 16; o; o >>= 1) dot += __shfl_xor_sync(0xffffffffu, dot, o);
            if (l == 0) a_s[i] = dot;
        }
        __syncthreads();
        if (w == 0) {
            float z = a_s[l];
            if (PASS == 2) {
                z += g_blog[((size_t)b * JJ + j) * IW + l];
            } else {
                g_blog[((size_t)b * JJ + j) * IW + l] = z;
            }
            float mx = z;
#pragma unroll
            for (int o = 16; o; o >>= 1) mx = fmaxf(mx, __shfl_xor_sync(0xffffffffu, mx, o));
            float p = __expf(z - mx);
            float sm = p;
#pragma unroll
            for (int o = 16; o; o >>= 1) sm += __shfl_xor_sync(0xffffffffu, sm, o);
            c_s[l] = p / sm;
        }
        __syncthreads();

#pragma unroll
        for (int s = 0; s < 4; s++) {
            float c = c_s[w + s * 8];
            sacc[s][0].x = fmaf(c, cur[s][0].x, sacc[s][0].x);
            sacc[s][0].y = fmaf(c, cur[s][0].y, sacc[s][0].y);
            sacc[s][0].z = fmaf(c, cur[s][0].z, sacc[s][0].z);
            sacc[s][0].w = fmaf(c, cur[s][0].w, sacc[s][0].w);
            sacc[s][1].x = fmaf(c, cur[s][1].x, sacc[s][1].x);
            sacc[s][1].y = fmaf(c, cur[s][1].y, sacc[s][1].y);
            sacc[s][1].z = fmaf(c, cur[s][1].z, sacc[s][1].z);
            sacc[s][1].w = fmaf(c, cur[s][1].w, sacc[s][1].w);
        }
#pragma unroll
        for (int s = 0; s < 4; s++) {
            cur[s][0] = nxt[s][0];
            cur[s][1] = nxt[s][1];
        }
    }

    float* So = g_S[sout_idx] + (size_t)b * IW * EE;
#pragma unroll
    for (int s = 0; s < 4; s++) {
        int i = w + s * 8;
        float* sp = &So[i * EE + l * 8];
        atomicAdd(sp + 0, sacc[s][0].x);
        atomicAdd(sp + 1, sacc[s][0].y);
        atomicAdd(sp + 2, sacc[s][0].z);
        atomicAdd(sp + 3, sacc[s][0].w);
        atomicAdd(sp + 4, sacc[s][1].x);
        atomicAdd(sp + 5, sacc[s][1].y);
        atomicAdd(sp + 6, sacc[s][1].z);
        atomicAdd(sp + 7, sacc[s][1].w);
    }
}

// ---------------- K8: output projection  out = v2 @ Wo^T + bo ----------------
__global__ void __launch_bounds__(256) k_proj_out(const float* __restrict__ Wo,
                                                  const float* __restrict__ bo,
                                                  float* __restrict__ out) {
    int b  = blockIdx.y;
    int db = blockIdx.x;
    __shared__ float vvs[32][EE];
    __shared__ float wos[32][33];

    int tid = threadIdx.x;
    const float4* vg4 = (const float4*)(g_V[2] + (size_t)b * IW * EE);
    float4* vv4 = (float4*)vvs;
    for (int idx = tid; idx < IW * EE / 4; idx += 256) vv4[idx] = vg4[idx];

    int dl = tid & 31;
    int n0 = (tid >> 5) * 4;
    float acc[4] = {0.f, 0.f, 0.f, 0.f};

    for (int et = 0; et < 8; et++) {
        __syncthreads();
        {
            int r = tid >> 5, c = tid & 31;
            for (int rr = r; rr < 32; rr += 8)
                wos[rr][c] = Wo[(size_t)(db * 32 + rr) * EE + et * 32 + c];
        }
        __syncthreads();
#pragma unroll
        for (int k = 0; k < 32; k++) {
            float wv = wos[dl][k];
#pragma unroll
            for (int r = 0; r < 4; r++)
                acc[r] = fmaf(vvs[n0 + r][et * 32 + k], wv, acc[r]);
        }
    }

    int dm = db * 32 + dl;
    float bv = bo[dm];
#pragma unroll
    for (int r = 0; r < 4; r++)
        out[((size_t)b * WORDS + n0 + r) * DIM + dm] = acc[r] + bv;
}

// ---------------- launch ----------------
extern "C" void kernel_launch(void* const* d_in, const int* in_sizes, int n_in,
                              void* d_out, int out_size) {
    const float* x    = (const float*)d_in[0];
    const float* W    = (const float*)d_in[1];
    const float* bias = (const float*)d_in[2];
    const float* Wi   = (const float*)d_in[3];
    const float* bi   = (const float*)d_in[4];
    const float* Wo   = (const float*)d_in[5];
    const float* bo   = (const float*)d_in[6];
    float* out = (float*)d_out;

    k_zero<<<(3 * BB * IW * EE) / 1024, 256>>>();
    k_proj_in<<<dim3(8, BB), 256>>>(x, Wi, bi);
    k_uhat<<<dim3(32, 32), 256>>>(W, bias);
    k_squash<<<BB * IW, 256>>>(0, 0, 1.0f / 32.0f);   // v0 from mean over j
    k_route<1><<<dim3(16, BB), 256>>>(0, 1);           // a0 -> blog, S1
    k_squash<<<BB * IW, 256>>>(1, 1, 1.0f);            // v1
    k_route<2><<<dim3(16, BB), 256>>>(1, 2);           // softmax(blog+a1), S2
    k_squash<<<BB * IW, 256>>>(2, 2, 1.0f);            // v2
    k_proj_out<<<dim3(8, BB), 256>>>(Wo, bo, out);
}